// round 1
// baseline (speedup 1.0000x reference)
#include <cuda_runtime.h>
#include <cuda_bf16.h>
#include <math.h>

// ---------------- problem constants ----------------
#define T_SEQ 1024
#define HID   2880
#define NH    64
#define KVH   8
#define GQ    8
#define DH    64
#define WIN   128
#define QKV_N 5120           // NH*DH + 2*KVH*DH
#define Q_OFF 0
#define K_OFF 4096           // NH*DH
#define V_OFF 4608           // NH*DH + KVH*DH
#define ATT_N 4096           // NH*DH

// ---------------- scratch (device globals; no allocation allowed) ----------------
__device__ float g_xn[(size_t)T_SEQ * HID];      // normalized input
__device__ float g_qkv[(size_t)T_SEQ * QKV_N];   // qkv (rope applied in place)
__device__ float g_attn[(size_t)T_SEQ * ATT_N];  // attention output
__device__ float g_cos[T_SEQ * 32];
__device__ float g_sin[T_SEQ * 32];

// ---------------- RMSNorm ----------------
__global__ void rmsnorm_kernel(const float* __restrict__ x,
                               const float* __restrict__ scale,
                               float* __restrict__ xn)
{
    const int t = blockIdx.x;
    const float4* xr = reinterpret_cast<const float4*>(x + (size_t)t * HID);
    float ss = 0.f;
    for (int i = threadIdx.x; i < HID / 4; i += 256) {
        float4 v = xr[i];
        ss += v.x * v.x + v.y * v.y + v.z * v.z + v.w * v.w;
    }
    __shared__ float red[8];
    for (int off = 16; off; off >>= 1) ss += __shfl_xor_sync(0xffffffffu, ss, off);
    if ((threadIdx.x & 31) == 0) red[threadIdx.x >> 5] = ss;
    __syncthreads();
    if (threadIdx.x < 32) {
        float v = (threadIdx.x < 8) ? red[threadIdx.x] : 0.f;
        for (int off = 4; off; off >>= 1) v += __shfl_xor_sync(0xffffffffu, v, off);
        if (threadIdx.x == 0) red[0] = v;
    }
    __syncthreads();
    const float r = rsqrtf(red[0] / (float)HID + 1e-5f);
    const float4* sr = reinterpret_cast<const float4*>(scale);
    float4* outr = reinterpret_cast<float4*>(xn + (size_t)t * HID);
    for (int i = threadIdx.x; i < HID / 4; i += 256) {
        float4 v = xr[i];
        float4 sv = sr[i];
        outr[i] = make_float4(v.x * r * sv.x, v.y * r * sv.y,
                              v.z * r * sv.z, v.w * r * sv.w);
    }
}

// ---------------- YaRN RoPE cos/sin table ----------------
__global__ void rope_table_kernel(const int* __restrict__ positions,
                                  float* __restrict__ gcos,
                                  float* __restrict__ gsin)
{
    const int t = blockIdx.x;
    const int i = threadIdx.x;  // 0..31
    const double pos = (double)positions[t];
    const double TWO_PI = 6.283185307179586476925286766559;
    const double BASE = 150000.0;
    const double freq = pow(BASE, (2.0 * i) / 64.0);
    const double conc = 0.1 * log(32.0) + 1.0;
    const double lo = 32.0 * log(4096.0 / (32.0 * TWO_PI)) / log(BASE);
    const double hi = 32.0 * log(4096.0 / (1.0 * TWO_PI)) / log(BASE);
    const double interp = 1.0 / (32.0 * freq);
    const double extrap = 1.0 / freq;
    double ramp = ((double)i - lo) / (hi - lo);
    ramp = fmin(fmax(ramp, 0.0), 1.0);
    const double mask = 1.0 - ramp;
    const double inv = interp * (1.0 - mask) + extrap * mask;
    const double ang = pos * inv;
    gcos[t * 32 + i] = (float)(cos(ang) * conc);
    gsin[t * 32 + i] = (float)(sin(ang) * conc);
}

// ---------------- apply RoPE in place to q and k ----------------
__global__ void rope_apply_kernel(float* __restrict__ qkv,
                                  const float* __restrict__ gcos,
                                  const float* __restrict__ gsin)
{
    const int t = blockIdx.y;
    const int hh = blockIdx.x;   // 0..71 (64 q heads + 8 k heads)
    const int i = threadIdx.x;   // 0..31
    const size_t base = (size_t)t * QKV_N +
                        (hh < NH ? (size_t)hh * DH : (size_t)K_OFF + (size_t)(hh - NH) * DH);
    const float c = gcos[t * 32 + i];
    const float s = gsin[t * 32 + i];
    const float x1 = qkv[base + i];
    const float x2 = qkv[base + 32 + i];
    qkv[base + i]      = x1 * c - x2 * s;
    qkv[base + 32 + i] = x2 * c + x1 * s;
}

// ---------------- tiled SGEMM: C = A(M,K) @ B(K,N) + bias (+ resid) ----------------
// 128x128 tile, BK=8, 256 threads, 8x8 per-thread microtile. M%128==0, K%8==0 assumed.
__global__ void __launch_bounds__(256, 2)
sgemm_bias_kernel(int M, int N, int K,
                  const float* __restrict__ A,
                  const float* __restrict__ B,
                  const float* __restrict__ bias,
                  const float* __restrict__ resid,
                  float* __restrict__ C)
{
    __shared__ float As[8][128];
    __shared__ float Bs[8][128];

    const int tid = threadIdx.x;
    const int rowBase = blockIdx.y * 128;
    const int colBase = blockIdx.x * 128;

    const int tr = (tid / 16) * 8;
    const int tc = (tid % 16) * 8;

    float acc[8][8];
#pragma unroll
    for (int i = 0; i < 8; i++)
#pragma unroll
        for (int j = 0; j < 8; j++) acc[i][j] = 0.f;

    const int aRow = tid >> 1;          // 0..127
    const int aCol = (tid & 1) * 4;     // 0 or 4
    const int bRow = tid >> 5;          // 0..7
    const int bCol = (tid & 31) * 4;    // 0..124

    for (int k0 = 0; k0 < K; k0 += 8) {
        float4 av = *reinterpret_cast<const float4*>(
            &A[(size_t)(rowBase + aRow) * K + k0 + aCol]);
        As[aCol + 0][aRow] = av.x;
        As[aCol + 1][aRow] = av.y;
        As[aCol + 2][aRow] = av.z;
        As[aCol + 3][aRow] = av.w;

        const int gc = colBase + bCol;
        const float* bp = &B[(size_t)(k0 + bRow) * N + gc];
        float4 bv;
        if (gc + 3 < N) {
            bv = *reinterpret_cast<const float4*>(bp);
        } else {
            bv.x = (gc + 0 < N) ? bp[0] : 0.f;
            bv.y = (gc + 1 < N) ? bp[1] : 0.f;
            bv.z = (gc + 2 < N) ? bp[2] : 0.f;
            bv.w = (gc + 3 < N) ? bp[3] : 0.f;
        }
        Bs[bRow][bCol + 0] = bv.x;
        Bs[bRow][bCol + 1] = bv.y;
        Bs[bRow][bCol + 2] = bv.z;
        Bs[bRow][bCol + 3] = bv.w;
        __syncthreads();

#pragma unroll
        for (int k = 0; k < 8; k++) {
            float4 a0 = *reinterpret_cast<const float4*>(&As[k][tr]);
            float4 a1 = *reinterpret_cast<const float4*>(&As[k][tr + 4]);
            float4 b0 = *reinterpret_cast<const float4*>(&Bs[k][tc]);
            float4 b1 = *reinterpret_cast<const float4*>(&Bs[k][tc + 4]);
            float a[8] = {a0.x, a0.y, a0.z, a0.w, a1.x, a1.y, a1.z, a1.w};
            float b[8] = {b0.x, b0.y, b0.z, b0.w, b1.x, b1.y, b1.z, b1.w};
#pragma unroll
            for (int i = 0; i < 8; i++)
#pragma unroll
                for (int j = 0; j < 8; j++) acc[i][j] += a[i] * b[j];
        }
        __syncthreads();
    }

#pragma unroll
    for (int i = 0; i < 8; i++) {
        const int r = rowBase + tr + i;
#pragma unroll
        for (int j = 0; j < 8; j++) {
            const int c = colBase + tc + j;
            if (c < N) {
                float v = acc[i][j] + bias[c];
                if (resid) v += resid[(size_t)r * N + c];
                C[(size_t)r * N + c] = v;
            }
        }
    }
}

// ---------------- sliding-window attention with sink ----------------
// one block per (head, query); 128 threads (one per key in window)
__global__ void attn_kernel(const float* __restrict__ qkv,
                            const float* __restrict__ sinks,
                            float* __restrict__ attn_out)
{
    const int h = blockIdx.x;    // 0..63
    const int t = blockIdx.y;    // 0..1023
    const int kvh = h >> 3;      // G=8
    const int tid = threadIdx.x; // 0..127

    __shared__ float qs[64];
    __shared__ float ps[128];
    __shared__ float red[4];
    __shared__ float outred[64];

    const float* qptr = qkv + (size_t)t * QKV_N + (size_t)h * DH;
    if (tid < 64) qs[tid] = qptr[tid];
    __syncthreads();

    const int j = t - (WIN - 1) + tid;  // key index this thread handles
    float s = -INFINITY;
    if (j >= 0) {
        const float* kptr = qkv + (size_t)j * QKV_N + K_OFF + (size_t)kvh * DH;
        float acc = 0.f;
#pragma unroll
        for (int d = 0; d < DH; d += 4) {
            float4 kv = *reinterpret_cast<const float4*>(&kptr[d]);
            acc += qs[d] * kv.x + qs[d + 1] * kv.y + qs[d + 2] * kv.z + qs[d + 3] * kv.w;
        }
        s = acc * 0.125f;  // D^-0.5
    }

    // block max
    float m = s;
    for (int off = 16; off; off >>= 1) m = fmaxf(m, __shfl_xor_sync(0xffffffffu, m, off));
    if ((tid & 31) == 0) red[tid >> 5] = m;
    __syncthreads();
    const float sink = sinks[h];
    const float M = fmaxf(fmaxf(fmaxf(red[0], red[1]), fmaxf(red[2], red[3])), sink);
    __syncthreads();  // everyone has read red before it is overwritten

    const float p = (j >= 0) ? expf(s - M) : 0.f;
    ps[tid] = p;
    float sm = p;
    for (int off = 16; off; off >>= 1) sm += __shfl_xor_sync(0xffffffffu, sm, off);
    if ((tid & 31) == 0) red[tid >> 5] = sm;
    __syncthreads();
    const float denom = red[0] + red[1] + red[2] + red[3] + expf(sink - M);
    const float inv = 1.f / denom;

    // PV: d = tid%64, two j-halves
    const int d = tid & 63;
    const int half = tid >> 6;
    const int base_j = t - (WIN - 1);
    float acc = 0.f;
#pragma unroll 4
    for (int jj = half * 64; jj < half * 64 + 64; jj++) {
        const int kidx = base_j + jj;
        if (kidx >= 0)
            acc += ps[jj] * qkv[(size_t)kidx * QKV_N + V_OFF + (size_t)kvh * DH + d];
    }
    if (half == 0) outred[d] = acc;
    __syncthreads();
    if (half == 1) outred[d] += acc;
    __syncthreads();
    if (tid < 64)
        attn_out[(size_t)t * ATT_N + (size_t)h * DH + tid] = outred[tid] * inv;
}

// ---------------- launch ----------------
extern "C" void kernel_launch(void* const* d_in, const int* in_sizes, int n_in,
                              void* d_out, int out_size)
{
    const float* hidden     = (const float*)d_in[0];
    const int*   positions  = (const int*)d_in[1];
    const float* norm_scale = (const float*)d_in[2];
    const float* w_qkv      = (const float*)d_in[3];
    const float* b_qkv      = (const float*)d_in[4];
    const float* w_out      = (const float*)d_in[5];
    const float* b_out      = (const float*)d_in[6];
    const float* sinks      = (const float*)d_in[7];
    float* out = (float*)d_out;

    float *xn, *qkv, *attn, *gcos, *gsin;
    cudaGetSymbolAddress((void**)&xn, g_xn);
    cudaGetSymbolAddress((void**)&qkv, g_qkv);
    cudaGetSymbolAddress((void**)&attn, g_attn);
    cudaGetSymbolAddress((void**)&gcos, g_cos);
    cudaGetSymbolAddress((void**)&gsin, g_sin);

    rmsnorm_kernel<<<T_SEQ, 256>>>(hidden, norm_scale, xn);
    rope_table_kernel<<<T_SEQ, 32>>>(positions, gcos, gsin);

    // qkv = xn @ w_qkv + b_qkv   (1024 x 2880 x 5120)
    sgemm_bias_kernel<<<dim3(QKV_N / 128, T_SEQ / 128), 256>>>(
        T_SEQ, QKV_N, HID, xn, w_qkv, b_qkv, nullptr, qkv);

    rope_apply_kernel<<<dim3(NH + KVH, T_SEQ), 32>>>(qkv, gcos, gsin);

    attn_kernel<<<dim3(NH, T_SEQ), 128>>>(qkv, sinks, attn);

    // out = attn @ w_out + b_out + hidden   (1024 x 4096 x 2880)
    sgemm_bias_kernel<<<dim3((HID + 127) / 128, T_SEQ / 128), 256>>>(
        T_SEQ, HID, ATT_N, attn, w_out, b_out, hidden, out);
}

// round 3
// speedup vs baseline: 1.0041x; 1.0041x over previous
#include <cuda_runtime.h>
#include <cuda_bf16.h>
#include <math.h>

// ---------------- problem constants ----------------
#define T_SEQ 1024
#define HID   2880
#define NH    64
#define KVH   8
#define DH    64
#define WIN   128
#define QKV_N 5120           // NH*DH + 2*KVH*DH
#define K_OFF 4096           // NH*DH
#define V_OFF 4608           // NH*DH + KVH*DH
#define ATT_N 4096           // NH*DH

// ---------------- scratch (device globals; no allocation allowed) ----------------
__device__ float g_xn[(size_t)T_SEQ * HID];      // normalized input
__device__ float g_qkv[(size_t)T_SEQ * QKV_N];   // qkv (rope applied in place)
__device__ float g_attn[(size_t)T_SEQ * ATT_N];  // attention output
__device__ float g_cos[T_SEQ * 32];
__device__ float g_sin[T_SEQ * 32];

// ---------------- RMSNorm ----------------
__global__ void rmsnorm_kernel(const float* __restrict__ x,
                               const float* __restrict__ scale,
                               float* __restrict__ xn)
{
    const int t = blockIdx.x;
    const float4* xr = reinterpret_cast<const float4*>(x + (size_t)t * HID);
    float ss = 0.f;
    for (int i = threadIdx.x; i < HID / 4; i += 256) {
        float4 v = xr[i];
        ss += v.x * v.x + v.y * v.y + v.z * v.z + v.w * v.w;
    }
    __shared__ float red[8];
    for (int off = 16; off; off >>= 1) ss += __shfl_xor_sync(0xffffffffu, ss, off);
    if ((threadIdx.x & 31) == 0) red[threadIdx.x >> 5] = ss;
    __syncthreads();
    if (threadIdx.x < 32) {
        float v = (threadIdx.x < 8) ? red[threadIdx.x] : 0.f;
        for (int off = 4; off; off >>= 1) v += __shfl_xor_sync(0xffffffffu, v, off);
        if (threadIdx.x == 0) red[0] = v;
    }
    __syncthreads();
    const float r = rsqrtf(red[0] / (float)HID + 1e-5f);
    const float4* sr = reinterpret_cast<const float4*>(scale);
    float4* outr = reinterpret_cast<float4*>(xn + (size_t)t * HID);
    for (int i = threadIdx.x; i < HID / 4; i += 256) {
        float4 v = xr[i];
        float4 sv = sr[i];
        outr[i] = make_float4(v.x * r * sv.x, v.y * r * sv.y,
                              v.z * r * sv.z, v.w * r * sv.w);
    }
}

// ---------------- YaRN RoPE cos/sin table ----------------
__global__ void rope_table_kernel(const int* __restrict__ positions,
                                  float* __restrict__ gcos,
                                  float* __restrict__ gsin)
{
    const int t = blockIdx.x;
    const int i = threadIdx.x;  // 0..31
    const double pos = (double)positions[t];
    const double TWO_PI = 6.283185307179586476925286766559;
    const double BASE = 150000.0;
    const double freq = pow(BASE, (2.0 * i) / 64.0);
    const double conc = 0.1 * log(32.0) + 1.0;
    const double lo = 32.0 * log(4096.0 / (32.0 * TWO_PI)) / log(BASE);
    const double hi = 32.0 * log(4096.0 / (1.0 * TWO_PI)) / log(BASE);
    const double interp = 1.0 / (32.0 * freq);
    const double extrap = 1.0 / freq;
    double ramp = ((double)i - lo) / (hi - lo);
    ramp = fmin(fmax(ramp, 0.0), 1.0);
    const double mask = 1.0 - ramp;
    const double inv = interp * (1.0 - mask) + extrap * mask;
    const double ang = pos * inv;
    gcos[t * 32 + i] = (float)(cos(ang) * conc);
    gsin[t * 32 + i] = (float)(sin(ang) * conc);
}

// ---------------- apply RoPE in place to q and k ----------------
__global__ void rope_apply_kernel(float* __restrict__ qkv,
                                  const float* __restrict__ gcos,
                                  const float* __restrict__ gsin)
{
    const int t = blockIdx.y;
    const int hh = blockIdx.x;   // 0..71 (64 q heads + 8 k heads)
    const int i = threadIdx.x;   // 0..31
    const size_t base = (size_t)t * QKV_N +
                        (hh < NH ? (size_t)hh * DH : (size_t)K_OFF + (size_t)(hh - NH) * DH);
    const float c = gcos[t * 32 + i];
    const float s = gsin[t * 32 + i];
    const float x1 = qkv[base + i];
    const float x2 = qkv[base + 32 + i];
    qkv[base + i]      = x1 * c - x2 * s;
    qkv[base + 32 + i] = x2 * c + x1 * s;
}

// ================= TF32 tensor-core GEMM =================
// C(M,N) = A(M,K) @ B(K,N) + bias (+resid).  M%128==0, K%32==0; N guarded.
// Block tile 128x128x32, 256 threads (8 warps in 2x4), warp tile 64x32,
// mma.sync.m16n8k8.tf32.  Smem holds fragment-permuted tiles so the compute
// loop does only conflict-free LDS.128 / LDS.64.

__device__ __forceinline__ unsigned f2tf(float x)
{
    unsigned r;
    asm("cvt.rna.tf32.f32 %0, %1;" : "=r"(r) : "f"(x));
    return r;
}

#define MMA_TF32(d, a, b) \
    asm volatile("mma.sync.aligned.m16n8k8.row.col.f32.tf32.tf32.f32 " \
                 "{%0,%1,%2,%3}, {%4,%5,%6,%7}, {%8,%9}, {%0,%1,%2,%3};" \
                 : "+f"(d.x), "+f"(d.y), "+f"(d.z), "+f"(d.w) \
                 : "r"(__float_as_uint(a.x)), "r"(__float_as_uint(a.y)), \
                   "r"(__float_as_uint(a.z)), "r"(__float_as_uint(a.w)), \
                   "r"(__float_as_uint(b.x)), "r"(__float_as_uint(b.y)))

__device__ __forceinline__ void ldg_tile_A(const float* __restrict__ A, int K,
                                           int rowBase, int k0, int tid, float4 v[4])
{
#pragma unroll
    for (int i = 0; i < 4; i++) {
        int f = tid + i * 256;
        int row = f >> 3, kq = f & 7;
        v[i] = *reinterpret_cast<const float4*>(
            &A[(size_t)(rowBase + row) * K + k0 + kq * 4]);
    }
}

__device__ __forceinline__ void sts_tile_A(float* __restrict__ smA, int tid,
                                           const float4 v[4])
{
#pragma unroll
    for (int i = 0; i < 4; i++) {
        int f = tid + i * 256;
        int row = f >> 3, kq = f & 7;
        int g = row >> 4, r16 = row & 15;
        int comp = (kq & 1) * 2 + (r16 >> 3);          // a0..a3 slot
        int base = (((kq >> 1) * 8 + g) * 32 + (r16 & 7) * 4);
        smA[(base + 0) * 4 + comp] = __uint_as_float(f2tf(v[i].x));
        smA[(base + 1) * 4 + comp] = __uint_as_float(f2tf(v[i].y));
        smA[(base + 2) * 4 + comp] = __uint_as_float(f2tf(v[i].z));
        smA[(base + 3) * 4 + comp] = __uint_as_float(f2tf(v[i].w));
    }
}

__device__ __forceinline__ void ldg_tile_B(const float* __restrict__ B, int N,
                                           int colBase, int k0, int tid, float4 v[4])
{
#pragma unroll
    for (int i = 0; i < 4; i++) {
        int f = tid + i * 256;
        int krow = f >> 5, cq = f & 31;
        int gc = colBase + cq * 4;
        if (gc < N) {
            v[i] = *reinterpret_cast<const float4*>(&B[(size_t)(k0 + krow) * N + gc]);
        } else {
            v[i] = make_float4(0.f, 0.f, 0.f, 0.f);
        }
    }
}

__device__ __forceinline__ void sts_tile_B(float* __restrict__ smB, int tid,
                                           const float4 v[4])
{
#pragma unroll
    for (int i = 0; i < 4; i++) {
        int f = tid + i * 256;
        int krow = f >> 5, cq = f & 31;
        int kstep = krow >> 3, hi = (krow >> 2) & 1, k4 = krow & 3;
        int ng = cq >> 1;
        int lane_b = (cq & 1) * 16 + k4;
        int base = (kstep * 16 + ng) * 32 + lane_b;
        smB[(base + 0) * 2 + hi] = __uint_as_float(f2tf(v[i].x));
        smB[(base + 4) * 2 + hi] = __uint_as_float(f2tf(v[i].y));
        smB[(base + 8) * 2 + hi] = __uint_as_float(f2tf(v[i].z));
        smB[(base + 12) * 2 + hi] = __uint_as_float(f2tf(v[i].w));
    }
}

__global__ void __launch_bounds__(256)
tf32gemm_kernel(int M, int N, int K,
                const float* __restrict__ A,
                const float* __restrict__ B,
                const float* __restrict__ bias,
                const float* __restrict__ resid,
                float* __restrict__ C)
{
    __shared__ float sm[8192];   // 32KB: A perm [0,4096), B perm [4096,8192)

    const int tid = threadIdx.x;
    const int lane = tid & 31;
    const int wid = tid >> 5;
    const int warp_m = wid >> 2;   // 0..1
    const int warp_n = wid & 3;    // 0..3
    const int rowBase = blockIdx.y * 128;
    const int colBase = blockIdx.x * 128;

    float4 acc[4][4];
#pragma unroll
    for (int i = 0; i < 4; i++)
#pragma unroll
        for (int j = 0; j < 4; j++) acc[i][j] = make_float4(0.f, 0.f, 0.f, 0.f);

    const int nk = K / 32;

    float4 av[4], bv[4];
    ldg_tile_A(A, K, rowBase, 0, tid, av);
    ldg_tile_B(B, N, colBase, 0, tid, bv);
    sts_tile_A(sm, tid, av);
    sts_tile_B(sm + 4096, tid, bv);
    __syncthreads();

    for (int kt = 0; kt < nk; kt++) {
        if (kt + 1 < nk) {
            ldg_tile_A(A, K, rowBase, (kt + 1) * 32, tid, av);
            ldg_tile_B(B, N, colBase, (kt + 1) * 32, tid, bv);
        }

        const float4* A4 = reinterpret_cast<const float4*>(sm);
        const float2* B2 = reinterpret_cast<const float2*>(sm + 4096);
#pragma unroll
        for (int ks = 0; ks < 4; ks++) {
            float4 af[4];
            float2 bf[4];
#pragma unroll
            for (int mm = 0; mm < 4; mm++)
                af[mm] = A4[(ks * 8 + warp_m * 4 + mm) * 32 + lane];
#pragma unroll
            for (int nn = 0; nn < 4; nn++)
                bf[nn] = B2[(ks * 16 + warp_n * 4 + nn) * 32 + lane];
#pragma unroll
            for (int mm = 0; mm < 4; mm++)
#pragma unroll
                for (int nn = 0; nn < 4; nn++)
                    MMA_TF32(acc[mm][nn], af[mm], bf[nn]);
        }
        __syncthreads();
        if (kt + 1 < nk) {
            sts_tile_A(sm, tid, av);
            sts_tile_B(sm + 4096, tid, bv);
        }
        __syncthreads();
    }

    // epilogue
#pragma unroll
    for (int mm = 0; mm < 4; mm++) {
        const int row0 = rowBase + (warp_m * 4 + mm) * 16 + (lane >> 2);
#pragma unroll
        for (int nn = 0; nn < 4; nn++) {
            const int col0 = colBase + (warp_n * 4 + nn) * 8 + (lane & 3) * 2;
            if (col0 < N) {
                const float4 a = acc[mm][nn];
                float2 r0 = make_float2(a.x + bias[col0], a.y + bias[col0 + 1]);
                float2 r1 = make_float2(a.z + bias[col0], a.w + bias[col0 + 1]);
                const size_t i0 = (size_t)row0 * N + col0;
                const size_t i1 = (size_t)(row0 + 8) * N + col0;
                if (resid) {
                    const float2 e0 = *reinterpret_cast<const float2*>(&resid[i0]);
                    const float2 e1 = *reinterpret_cast<const float2*>(&resid[i1]);
                    r0.x += e0.x; r0.y += e0.y;
                    r1.x += e1.x; r1.y += e1.y;
                }
                *reinterpret_cast<float2*>(&C[i0]) = r0;
                *reinterpret_cast<float2*>(&C[i1]) = r1;
            }
        }
    }
}

// ---------------- sliding-window attention with sink ----------------
// one block per (head, query); 128 threads (one per key in window)
__global__ void attn_kernel(const float* __restrict__ qkv,
                            const float* __restrict__ sinks,
                            float* __restrict__ attn_out)
{
    const int h = blockIdx.x;    // 0..63
    const int t = blockIdx.y;    // 0..1023
    const int kvh = h >> 3;      // G=8
    const int tid = threadIdx.x; // 0..127

    __shared__ float qs[64];
    __shared__ float ps[128];
    __shared__ float red[4];
    __shared__ float outred[64];

    const float* qptr = qkv + (size_t)t * QKV_N + (size_t)h * DH;
    if (tid < 64) qs[tid] = qptr[tid];
    __syncthreads();

    const int j = t - (WIN - 1) + tid;  // key index this thread handles
    float s = -INFINITY;
    if (j >= 0) {
        const float* kptr = qkv + (size_t)j * QKV_N + K_OFF + (size_t)kvh * DH;
        float acc = 0.f;
#pragma unroll
        for (int d = 0; d < DH; d += 4) {
            float4 kv = *reinterpret_cast<const float4*>(&kptr[d]);
            acc += qs[d] * kv.x + qs[d + 1] * kv.y + qs[d + 2] * kv.z + qs[d + 3] * kv.w;
        }
        s = acc * 0.125f;  // D^-0.5
    }

    // block max
    float m = s;
    for (int off = 16; off; off >>= 1) m = fmaxf(m, __shfl_xor_sync(0xffffffffu, m, off));
    if ((tid & 31) == 0) red[tid >> 5] = m;
    __syncthreads();
    const float sink = sinks[h];
    const float M = fmaxf(fmaxf(fmaxf(red[0], red[1]), fmaxf(red[2], red[3])), sink);
    __syncthreads();  // everyone has read red before it is overwritten

    const float p = (j >= 0) ? expf(s - M) : 0.f;
    ps[tid] = p;
    float sm = p;
    for (int off = 16; off; off >>= 1) sm += __shfl_xor_sync(0xffffffffu, sm, off);
    if ((tid & 31) == 0) red[tid >> 5] = sm;
    __syncthreads();
    const float denom = red[0] + red[1] + red[2] + red[3] + expf(sink - M);
    const float inv = 1.f / denom;

    // PV: d = tid%64, two j-halves
    const int d = tid & 63;
    const int half = tid >> 6;
    const int base_j = t - (WIN - 1);
    float acc = 0.f;
#pragma unroll 4
    for (int jj = half * 64; jj < half * 64 + 64; jj++) {
        const int kidx = base_j + jj;
        if (kidx >= 0)
            acc += ps[jj] * qkv[(size_t)kidx * QKV_N + V_OFF + (size_t)kvh * DH + d];
    }
    if (half == 0) outred[d] = acc;
    __syncthreads();
    if (half == 1) outred[d] += acc;
    __syncthreads();
    if (tid < 64)
        attn_out[(size_t)t * ATT_N + (size_t)h * DH + tid] = outred[tid] * inv;
}

// ---------------- launch ----------------
extern "C" void kernel_launch(void* const* d_in, const int* in_sizes, int n_in,
                              void* d_out, int out_size)
{
    const float* hidden     = (const float*)d_in[0];
    const int*   positions  = (const int*)d_in[1];
    const float* norm_scale = (const float*)d_in[2];
    const float* w_qkv      = (const float*)d_in[3];
    const float* b_qkv      = (const float*)d_in[4];
    const float* w_out      = (const float*)d_in[5];
    const float* b_out      = (const float*)d_in[6];
    const float* sinks      = (const float*)d_in[7];
    float* out = (float*)d_out;

    float *xn, *qkv, *attn, *gcos, *gsin;
    cudaGetSymbolAddress((void**)&xn, g_xn);
    cudaGetSymbolAddress((void**)&qkv, g_qkv);
    cudaGetSymbolAddress((void**)&attn, g_attn);
    cudaGetSymbolAddress((void**)&gcos, g_cos);
    cudaGetSymbolAddress((void**)&gsin, g_sin);

    rmsnorm_kernel<<<T_SEQ, 256>>>(hidden, norm_scale, xn);
    rope_table_kernel<<<T_SEQ, 32>>>(positions, gcos, gsin);

    // qkv = xn @ w_qkv + b_qkv   (1024 x 5120 x 2880)
    tf32gemm_kernel<<<dim3(QKV_N / 128, T_SEQ / 128), 256>>>(
        T_SEQ, QKV_N, HID, xn, w_qkv, b_qkv, nullptr, qkv);

    rope_apply_kernel<<<dim3(NH + KVH, T_SEQ), 32>>>(qkv, gcos, gsin);

    attn_kernel<<<dim3(NH, T_SEQ), 128>>>(qkv, sinks, attn);

    // out = attn @ w_out + b_out + hidden   (1024 x 2880 x 4096)
    tf32gemm_kernel<<<dim3((HID + 127) / 128, T_SEQ / 128), 256>>>(
        T_SEQ, HID, ATT_N, attn, w_out, b_out, hidden, out);
}